// round 5
// baseline (speedup 1.0000x reference)
#include <cuda_runtime.h>

#define H 128
#define MAXN 100000
#define TPB 256
#define WARPS 8
#define RPW_L 8   // rows/warp, layer kernel
#define RPW_UV 4  // rows/warp, uv kernel

// ---------------- scratch (device globals; no allocations anywhere) ----------------
__device__ __align__(128) float g_agg[MAXN * H];
__device__ __align__(128) float g_deg[MAXN];
__device__ __align__(128) float g_x1[MAXN * H];
__device__ __align__(128) float g_u[MAXN * H];
__device__ __align__(128) float g_v[MAXN * H];

typedef unsigned long long u64;

// ---------------- f32x2 packed helpers ----------------
static __device__ __forceinline__ void fma2(u64& d, u64 a, u64 b) {
    asm("fma.rn.f32x2 %0, %1, %2, %0;" : "+l"(d) : "l"(a), "l"(b));
}
static __device__ __forceinline__ float2 upk(u64 a) {
    float2 r;
    asm("mov.b64 {%0,%1}, %2;" : "=f"(r.x), "=f"(r.y) : "l"(a));
    return r;
}

// ---------------- zero ----------------
__global__ void zero_kernel(float4* p, int n4) {
    int i = blockIdx.x * blockDim.x + threadIdx.x;
    if (i < n4) p[i] = make_float4(0.f, 0.f, 0.f, 0.f);
}

// ---------------- edge scatter: agg[dst] += x[src], deg[dst] += 1 ----------------
__global__ void scatter_kernel(const float* __restrict__ x, const int* __restrict__ src,
                               const int* __restrict__ dst, float* __restrict__ agg,
                               float* __restrict__ deg, int nE) {
    int lane = threadIdx.x & 31;
    int w = (blockIdx.x * blockDim.x + threadIdx.x) >> 5;
    int nw = (gridDim.x * blockDim.x) >> 5;
    for (int e = w; e < nE; e += nw) {
        size_t s = (size_t)src[e];
        size_t d = (size_t)dst[e];
        float4 val = *(const float4*)(x + s * H + (size_t)lane * 4);
        float* p = agg + d * H + (size_t)lane * 4;
        asm volatile("red.global.add.v4.f32 [%0], {%1,%2,%3,%4};" ::"l"(p), "f"(val.x),
                         "f"(val.y), "f"(val.z), "f"(val.w)
                     : "memory");
        if (deg != nullptr && lane == 0) atomicAdd(deg + d, 1.0f);
    }
}

// ---------------- fused SAGE layer: out = relu((agg/max(deg,1))@Wl + x@Wr + b) ----------------
// K=256 (mean|x). Weights in smem as k-pair-interleaved float2: Wp[kp*H+c] = (W[2kp][c], W[2kp+1][c]).
// f32x2 accumulators split over k-parity; epilogue sums the halves. Zero packing movs.
__global__ void __launch_bounds__(TPB, 1)
layer_kernel(const float* __restrict__ x, const float* __restrict__ agg,
             const float* __restrict__ deg, const float* __restrict__ Wl,
             const float* __restrict__ Wr, const float* __restrict__ bias,
             float* __restrict__ out, int n) {
    extern __shared__ float sm[];
    float2* Wp = (float2*)sm;                 // 128 kp * 128 c float2 = 128KB
    float* stage = sm + 2 * 128 * H;          // WARPS * RPW_L * 256 floats = 64KB
    for (int i = threadIdx.x; i < 128 * H; i += TPB) {
        int kp = i >> 7, c = i & 127;
        int k2 = kp * 2;
        float w0, w1;
        if (k2 < H) {
            w0 = Wl[k2 * H + c];
            w1 = Wl[(k2 + 1) * H + c];
        } else {
            w0 = Wr[(k2 - H) * H + c];
            w1 = Wr[(k2 - H + 1) * H + c];
        }
        Wp[i] = make_float2(w0, w1);
    }
    __syncthreads();
    const int warp = threadIdx.x >> 5, lane = threadIdx.x & 31;
    const int c0 = lane * 4;
    float* st = stage + warp * (RPW_L * 256);
    const float4 b4 = *(const float4*)(bias + c0);

    for (int base = blockIdx.x * (WARPS * RPW_L) + warp * RPW_L; base < n;
         base += gridDim.x * (WARPS * RPW_L)) {
#pragma unroll
        for (int r = 0; r < RPW_L; r++) {
            int row = base + r;
            if (row < n) {
                float rd = 1.0f / fmaxf(deg[row], 1.0f);
                float4 av = *(const float4*)(agg + (size_t)row * H + c0);
                float4 xv = *(const float4*)(x + (size_t)row * H + c0);
                av.x *= rd; av.y *= rd; av.z *= rd; av.w *= rd;
                *(float4*)(st + r * 256 + c0) = av;
                *(float4*)(st + r * 256 + 128 + c0) = xv;
            }
        }
        __syncwarp();

        u64 acc[RPW_L][4];
#pragma unroll
        for (int r = 0; r < RPW_L; r++)
#pragma unroll
            for (int c = 0; c < 4; c++) acc[r][c] = 0ull;

#pragma unroll 4
        for (int k4 = 0; k4 < 64; k4++) {
            // pairs kp0=2k4 (k=4k4,4k4+1), kp1=2k4+1 (k=4k4+2,4k4+3)
            const ulonglong2* wr0 = (const ulonglong2*)(Wp + (2 * k4) * H + c0);
            const ulonglong2* wr1 = (const ulonglong2*)(Wp + (2 * k4 + 1) * H + c0);
            ulonglong2 wA0 = wr0[0], wA1 = wr0[1];
            ulonglong2 wB0 = wr1[0], wB1 = wr1[1];
#pragma unroll
            for (int r = 0; r < RPW_L; r++) {
                u64 aA = *(const u64*)(st + r * 256 + 4 * k4);
                u64 aB = *(const u64*)(st + r * 256 + 4 * k4 + 2);
                fma2(acc[r][0], wA0.x, aA);
                fma2(acc[r][1], wA0.y, aA);
                fma2(acc[r][2], wA1.x, aA);
                fma2(acc[r][3], wA1.y, aA);
                fma2(acc[r][0], wB0.x, aB);
                fma2(acc[r][1], wB0.y, aB);
                fma2(acc[r][2], wB1.x, aB);
                fma2(acc[r][3], wB1.y, aB);
            }
        }

#pragma unroll
        for (int r = 0; r < RPW_L; r++) {
            int row = base + r;
            if (row < n) {
                float2 p0 = upk(acc[r][0]), p1 = upk(acc[r][1]);
                float2 p2 = upk(acc[r][2]), p3 = upk(acc[r][3]);
                float4 o;
                o.x = fmaxf(p0.x + p0.y + b4.x, 0.f);
                o.y = fmaxf(p1.x + p1.y + b4.y, 0.f);
                o.z = fmaxf(p2.x + p2.y + b4.z, 0.f);
                o.w = fmaxf(p3.x + p3.y + b4.w, 0.f);
                *(float4*)(out + (size_t)row * H + c0) = o;
            }
        }
        __syncwarp();
    }
}

// ---------------- u/v precompute as one [n,128]x[128,256] GEMM (u||v) ----------------
// Wp[kp*256+cc] = pair over k of W1 rows: cc<128 -> u cols (W1 rows 2kp,2kp+1),
//                 cc>=128 -> v cols (W1 rows 128+2kp, 129+2kp).
__global__ void __launch_bounds__(TPB, 1)
uv_kernel(const float* __restrict__ x, const float* __restrict__ W1, float* __restrict__ u,
          float* __restrict__ v, int n) {
    extern __shared__ float sm[];
    float2* Wp = (float2*)sm;              // 64 kp * 256 cc float2 = 128KB
    float* stage = sm + 2 * 64 * 256;      // WARPS * RPW_UV * 128 floats = 16KB
    for (int i = threadIdx.x; i < 64 * 256; i += TPB) {
        int kp = i >> 8, cc = i & 255;
        int c = cc & 127;
        int r2 = 2 * kp + ((cc < 128) ? 0 : 128);
        Wp[i] = make_float2(W1[r2 * H + c], W1[(r2 + 1) * H + c]);
    }
    __syncthreads();
    const int warp = threadIdx.x >> 5, lane = threadIdx.x & 31;
    const int c0 = lane * 4;
    float* st = stage + warp * (RPW_UV * H);

    for (int base = blockIdx.x * (WARPS * RPW_UV) + warp * RPW_UV; base < n;
         base += gridDim.x * (WARPS * RPW_UV)) {
#pragma unroll
        for (int r = 0; r < RPW_UV; r++) {
            int row = base + r;
            if (row < n) {
                float4 xv = *(const float4*)(x + (size_t)row * H + c0);
                *(float4*)(st + r * H + c0) = xv;
            }
        }
        __syncwarp();

        u64 au[RPW_UV][4], av[RPW_UV][4];
#pragma unroll
        for (int r = 0; r < RPW_UV; r++)
#pragma unroll
            for (int c = 0; c < 4; c++) { au[r][c] = 0ull; av[r][c] = 0ull; }

#pragma unroll 4
        for (int k4 = 0; k4 < 32; k4++) {
            const ulonglong2* wu0 = (const ulonglong2*)(Wp + (2 * k4) * 256 + c0);
            const ulonglong2* wv0 = (const ulonglong2*)(Wp + (2 * k4) * 256 + 128 + c0);
            const ulonglong2* wu1 = (const ulonglong2*)(Wp + (2 * k4 + 1) * 256 + c0);
            const ulonglong2* wv1 = (const ulonglong2*)(Wp + (2 * k4 + 1) * 256 + 128 + c0);
            ulonglong2 uA0 = wu0[0], uA1 = wu0[1], vA0 = wv0[0], vA1 = wv0[1];
            ulonglong2 uB0 = wu1[0], uB1 = wu1[1], vB0 = wv1[0], vB1 = wv1[1];
#pragma unroll
            for (int r = 0; r < RPW_UV; r++) {
                u64 aA = *(const u64*)(st + r * H + 4 * k4);
                u64 aB = *(const u64*)(st + r * H + 4 * k4 + 2);
                fma2(au[r][0], uA0.x, aA);
                fma2(au[r][1], uA0.y, aA);
                fma2(au[r][2], uA1.x, aA);
                fma2(au[r][3], uA1.y, aA);
                fma2(av[r][0], vA0.x, aA);
                fma2(av[r][1], vA0.y, aA);
                fma2(av[r][2], vA1.x, aA);
                fma2(av[r][3], vA1.y, aA);
                fma2(au[r][0], uB0.x, aB);
                fma2(au[r][1], uB0.y, aB);
                fma2(au[r][2], uB1.x, aB);
                fma2(au[r][3], uB1.y, aB);
                fma2(av[r][0], vB0.x, aB);
                fma2(av[r][1], vB0.y, aB);
                fma2(av[r][2], vB1.x, aB);
                fma2(av[r][3], vB1.y, aB);
            }
        }

#pragma unroll
        for (int r = 0; r < RPW_UV; r++) {
            int row = base + r;
            if (row < n) {
                float2 a0 = upk(au[r][0]), a1 = upk(au[r][1]), a2 = upk(au[r][2]),
                       a3 = upk(au[r][3]);
                float2 b0 = upk(av[r][0]), b1 = upk(av[r][1]), b2 = upk(av[r][2]),
                       b3 = upk(av[r][3]);
                *(float4*)(u + (size_t)row * H + c0) =
                    make_float4(a0.x + a0.y, a1.x + a1.y, a2.x + a2.y, a3.x + a3.y);
                *(float4*)(v + (size_t)row * H + c0) =
                    make_float4(b0.x + b0.y, b1.x + b1.y, b2.x + b2.y, b3.x + b3.y);
            }
        }
        __syncwarp();
    }
}

// ---------------- edge classifier: logits = relu(u[s]+v[d]+b1) @ W2 + b2 ----------------
__global__ void edge_kernel(const float* __restrict__ u, const float* __restrict__ v,
                            const int* __restrict__ qs, const int* __restrict__ qd,
                            const float* __restrict__ b1, const float* __restrict__ W2,
                            const float* __restrict__ b2, float* __restrict__ out, int nq) {
    __shared__ float W2s[H * 8];
    __shared__ float b1s[H];
    __shared__ float b2s[8];
    for (int i = threadIdx.x; i < H * 8; i += blockDim.x) W2s[i] = W2[i];
    for (int i = threadIdx.x; i < H; i += blockDim.x) b1s[i] = b1[i];
    if (threadIdx.x < 8) b2s[threadIdx.x] = b2[threadIdx.x];
    __syncthreads();

    int idx = blockIdx.x * blockDim.x + threadIdx.x;
    int stride = gridDim.x * blockDim.x;
    for (int e = idx; e < nq; e += stride) {
        size_t s = (size_t)qs[e];
        size_t d = (size_t)qd[e];
        const float4* ur = (const float4*)(u + s * H);
        const float4* vr = (const float4*)(v + d * H);
        float lg[8];
#pragma unroll
        for (int c = 0; c < 8; c++) lg[c] = b2s[c];
#pragma unroll 8
        for (int k4 = 0; k4 < 32; k4++) {
            float4 a = __ldg(ur + k4);
            float4 b = __ldg(vr + k4);
            float h0 = fmaxf(a.x + b.x + b1s[k4 * 4 + 0], 0.f);
            float h1 = fmaxf(a.y + b.y + b1s[k4 * 4 + 1], 0.f);
            float h2 = fmaxf(a.z + b.z + b1s[k4 * 4 + 2], 0.f);
            float h3 = fmaxf(a.w + b.w + b1s[k4 * 4 + 3], 0.f);
#pragma unroll
            for (int c = 0; c < 8; c++) {
                lg[c] += h0 * W2s[(k4 * 4 + 0) * 8 + c];
                lg[c] += h1 * W2s[(k4 * 4 + 1) * 8 + c];
                lg[c] += h2 * W2s[(k4 * 4 + 2) * 8 + c];
                lg[c] += h3 * W2s[(k4 * 4 + 3) * 8 + c];
            }
        }
        float4* op = (float4*)(out + (size_t)e * 8);
        op[0] = make_float4(lg[0], lg[1], lg[2], lg[3]);
        op[1] = make_float4(lg[4], lg[5], lg[6], lg[7]);
    }
}

// ---------------- host ----------------
#define SMEM_LAYER ((2 * 128 * H + WARPS * RPW_L * 256) * 4)  // 128KB + 64KB
#define SMEM_UV ((2 * 64 * 256 + WARPS * RPW_UV * 128) * 4)   // 128KB + 16KB

extern "C" void kernel_launch(void* const* d_in, const int* in_sizes, int n_in, void* d_out,
                              int out_size) {
    const float* node_emb = (const float*)d_in[0];
    const float* Wl0 = (const float*)d_in[1];
    const float* bl0 = (const float*)d_in[2];
    const float* Wr0 = (const float*)d_in[3];
    const float* Wl1 = (const float*)d_in[4];
    const float* bl1 = (const float*)d_in[5];
    const float* Wr1 = (const float*)d_in[6];
    const float* mW1 = (const float*)d_in[7];
    const float* mb1 = (const float*)d_in[8];
    const float* mW2 = (const float*)d_in[9];
    const float* mb2 = (const float*)d_in[10];
    const int* eidx = (const int*)d_in[11];  // int32 (JAX x64 disabled)
    const int* eq = (const int*)d_in[12];    // int32

    const int n = in_sizes[0] / H;    // 100000
    const int nE = in_sizes[11] / 2;  // 1600000
    const int nq = in_sizes[12] / 2;  // 500000

    float *agg, *deg, *x1, *u, *v;
    cudaGetSymbolAddress((void**)&agg, g_agg);
    cudaGetSymbolAddress((void**)&deg, g_deg);
    cudaGetSymbolAddress((void**)&x1, g_x1);
    cudaGetSymbolAddress((void**)&u, g_u);
    cudaGetSymbolAddress((void**)&v, g_v);

    int sms = 148;
    cudaDeviceGetAttribute(&sms, cudaDevAttrMultiProcessorCount, 0);
    cudaFuncSetAttribute(layer_kernel, cudaFuncAttributeMaxDynamicSharedMemorySize, SMEM_LAYER);
    cudaFuncSetAttribute(uv_kernel, cudaFuncAttributeMaxDynamicSharedMemorySize, SMEM_UV);

    const int n4 = n * H / 4;
    const int scatter_blocks = sms * 16;

    // layer 0
    zero_kernel<<<(n4 + 255) / 256, 256>>>((float4*)agg, n4);
    zero_kernel<<<(n / 4 + 255) / 256, 256>>>((float4*)deg, n / 4);
    scatter_kernel<<<scatter_blocks, 256>>>(node_emb, eidx, eidx + nE, agg, deg, nE);
    layer_kernel<<<sms, TPB, SMEM_LAYER>>>(node_emb, agg, deg, Wl0, Wr0, bl0, x1, n);

    // layer 1 (in-place on x1; row-local so safe)
    zero_kernel<<<(n4 + 255) / 256, 256>>>((float4*)agg, n4);
    scatter_kernel<<<scatter_blocks, 256>>>(x1, eidx, eidx + nE, agg, nullptr, nE);
    layer_kernel<<<sms, TPB, SMEM_LAYER>>>(x1, agg, deg, Wl1, Wr1, bl1, x1, n);

    // edge classifier
    uv_kernel<<<sms, TPB, SMEM_UV>>>(x1, mW1, u, v, n);
    edge_kernel<<<(nq + TPB - 1) / TPB, TPB>>>(u, v, eq, eq + nq, mb1, mW2, mb2, (float*)d_out,
                                               nq);
}

// round 6
// speedup vs baseline: 1.1794x; 1.1794x over previous
#include <cuda_runtime.h>

#define H 128
#define MAXN 100000
#define TPB 512
#define WARPS 16
#define RPW_L 6   // rows/warp, layer kernel
#define RPW_UV 4  // rows/warp, uv kernel

// ---------------- scratch (device globals; no allocations anywhere) ----------------
__device__ __align__(128) float g_agg[MAXN * H];
__device__ __align__(128) float g_deg[MAXN];
__device__ __align__(128) float g_x1[MAXN * H];
__device__ __align__(128) float g_u[MAXN * H];
__device__ __align__(128) float g_v[MAXN * H];

typedef unsigned long long u64;

// ---------------- f32x2 packed helpers ----------------
static __device__ __forceinline__ u64 pk2(float a, float b) {
    u64 r;
    asm("mov.b64 %0, {%1,%2};" : "=l"(r) : "f"(a), "f"(b));
    return r;
}
static __device__ __forceinline__ void fma2(u64& d, u64 a, u64 b) {
    asm("fma.rn.f32x2 %0, %1, %2, %0;" : "+l"(d) : "l"(a), "l"(b));
}
static __device__ __forceinline__ float2 upk(u64 a) {
    float2 r;
    asm("mov.b64 {%0,%1}, %2;" : "=f"(r.x), "=f"(r.y) : "l"(a));
    return r;
}

// ---------------- zero ----------------
__global__ void zero_kernel(float4* p, int n4) {
    int i = blockIdx.x * blockDim.x + threadIdx.x;
    if (i < n4) p[i] = make_float4(0.f, 0.f, 0.f, 0.f);
}

// ---------------- edge scatter: agg[dst] += x[src], deg[dst] += 1 ----------------
__global__ void scatter_kernel(const float* __restrict__ x, const int* __restrict__ src,
                               const int* __restrict__ dst, float* __restrict__ agg,
                               float* __restrict__ deg, int nE) {
    int lane = threadIdx.x & 31;
    int w = (blockIdx.x * blockDim.x + threadIdx.x) >> 5;
    int nw = (gridDim.x * blockDim.x) >> 5;
    for (int e = w; e < nE; e += nw) {
        size_t s = (size_t)src[e];
        size_t d = (size_t)dst[e];
        float4 val = *(const float4*)(x + s * H + (size_t)lane * 4);
        float* p = agg + d * H + (size_t)lane * 4;
        asm volatile("red.global.add.v4.f32 [%0], {%1,%2,%3,%4};" ::"l"(p), "f"(val.x),
                         "f"(val.y), "f"(val.z), "f"(val.w)
                     : "memory");
        if (deg != nullptr && lane == 0) atomicAdd(deg + d, 1.0f);
    }
}

// ---------------- fused SAGE layer: out = relu((agg/max(deg,1))@Wl + x@Wr + b) ----------------
// R3 inner loop (column-packed f32x2, pk2(a,a) duplication) at 16 warps/SM for latency hiding.
__global__ void __launch_bounds__(TPB, 1)
layer_kernel(const float* __restrict__ x, const float* __restrict__ agg,
             const float* __restrict__ deg, const float* __restrict__ Wl,
             const float* __restrict__ Wr, const float* __restrict__ bias,
             float* __restrict__ out, int n) {
    extern __shared__ float sm[];
    float* Ws = sm;               // 256*128 floats = 128KB (Wl rows then Wr rows)
    float* stage = sm + 256 * H;  // WARPS * RPW_L * 256 floats = 96KB
    for (int i = threadIdx.x; i < H * H; i += TPB) {
        Ws[i] = Wl[i];
        Ws[H * H + i] = Wr[i];
    }
    __syncthreads();
    const int warp = threadIdx.x >> 5, lane = threadIdx.x & 31;
    const int c0 = lane * 4;
    float* st = stage + warp * (RPW_L * 256);
    const float4 b4 = *(const float4*)(bias + c0);

    for (int base = blockIdx.x * (WARPS * RPW_L) + warp * RPW_L; base < n;
         base += gridDim.x * (WARPS * RPW_L)) {
#pragma unroll
        for (int r = 0; r < RPW_L; r++) {
            int row = base + r;
            if (row < n) {
                float rd = 1.0f / fmaxf(deg[row], 1.0f);
                float4 av = *(const float4*)(agg + (size_t)row * H + c0);
                float4 xv = *(const float4*)(x + (size_t)row * H + c0);
                av.x *= rd; av.y *= rd; av.z *= rd; av.w *= rd;
                *(float4*)(st + r * 256 + c0) = av;
                *(float4*)(st + r * 256 + 128 + c0) = xv;
            }
        }
        __syncwarp();

        u64 acc0[RPW_L], acc1[RPW_L];
#pragma unroll
        for (int r = 0; r < RPW_L; r++) { acc0[r] = 0ull; acc1[r] = 0ull; }

#pragma unroll 2
        for (int k4 = 0; k4 < 64; k4++) {
            float4 a4[RPW_L];
#pragma unroll
            for (int r = 0; r < RPW_L; r++) a4[r] = *(const float4*)(st + r * 256 + k4 * 4);
#pragma unroll
            for (int j = 0; j < 4; j++) {
                float4 wv = *(const float4*)(Ws + (k4 * 4 + j) * H + c0);
                u64 w01 = pk2(wv.x, wv.y), w23 = pk2(wv.z, wv.w);
#pragma unroll
                for (int r = 0; r < RPW_L; r++) {
                    float a = (j == 0) ? a4[r].x : (j == 1) ? a4[r].y : (j == 2) ? a4[r].z
                                                                                 : a4[r].w;
                    u64 a2 = pk2(a, a);
                    fma2(acc0[r], w01, a2);
                    fma2(acc1[r], w23, a2);
                }
            }
        }

#pragma unroll
        for (int r = 0; r < RPW_L; r++) {
            int row = base + r;
            if (row < n) {
                float2 p0 = upk(acc0[r]), p1 = upk(acc1[r]);
                float4 o;
                o.x = fmaxf(p0.x + b4.x, 0.f);
                o.y = fmaxf(p0.y + b4.y, 0.f);
                o.z = fmaxf(p1.x + b4.z, 0.f);
                o.w = fmaxf(p1.y + b4.w, 0.f);
                *(float4*)(out + (size_t)row * H + c0) = o;
            }
        }
        __syncwarp();
    }
}

// ---------------- u/v precompute: u = x@W1[0:128,:], v = x@W1[128:256,:] ----------------
__global__ void __launch_bounds__(TPB, 1)
uv_kernel(const float* __restrict__ x, const float* __restrict__ W1, float* __restrict__ u,
          float* __restrict__ v, int n) {
    extern __shared__ float sm[];
    float* Ws = sm;               // full W1: 256*128 floats = 128KB
    float* stage = sm + 256 * H;  // WARPS * RPW_UV * 128 floats = 32KB
    for (int i = threadIdx.x; i < 256 * H; i += TPB) Ws[i] = W1[i];
    __syncthreads();
    const int warp = threadIdx.x >> 5, lane = threadIdx.x & 31;
    const int c0 = lane * 4;
    float* st = stage + warp * (RPW_UV * H);

    for (int base = blockIdx.x * (WARPS * RPW_UV) + warp * RPW_UV; base < n;
         base += gridDim.x * (WARPS * RPW_UV)) {
#pragma unroll
        for (int r = 0; r < RPW_UV; r++) {
            int row = base + r;
            if (row < n) {
                float4 xv = *(const float4*)(x + (size_t)row * H + c0);
                *(float4*)(st + r * H + c0) = xv;
            }
        }
        __syncwarp();

        u64 ua0[RPW_UV], ua1[RPW_UV], va0[RPW_UV], va1[RPW_UV];
#pragma unroll
        for (int r = 0; r < RPW_UV; r++) { ua0[r] = 0ull; ua1[r] = 0ull; va0[r] = 0ull; va1[r] = 0ull; }

#pragma unroll 2
        for (int k4 = 0; k4 < 32; k4++) {
            float4 a4[RPW_UV];
#pragma unroll
            for (int r = 0; r < RPW_UV; r++) a4[r] = *(const float4*)(st + r * H + k4 * 4);
#pragma unroll
            for (int j = 0; j < 4; j++) {
                int k = k4 * 4 + j;
                float4 wt = *(const float4*)(Ws + k * H + c0);
                float4 wb = *(const float4*)(Ws + (128 + k) * H + c0);
                u64 wt01 = pk2(wt.x, wt.y), wt23 = pk2(wt.z, wt.w);
                u64 wb01 = pk2(wb.x, wb.y), wb23 = pk2(wb.z, wb.w);
#pragma unroll
                for (int r = 0; r < RPW_UV; r++) {
                    float a = (j == 0) ? a4[r].x : (j == 1) ? a4[r].y : (j == 2) ? a4[r].z
                                                                                 : a4[r].w;
                    u64 a2 = pk2(a, a);
                    fma2(ua0[r], wt01, a2);
                    fma2(ua1[r], wt23, a2);
                    fma2(va0[r], wb01, a2);
                    fma2(va1[r], wb23, a2);
                }
            }
        }

#pragma unroll
        for (int r = 0; r < RPW_UV; r++) {
            int row = base + r;
            if (row < n) {
                float2 p0 = upk(ua0[r]), p1 = upk(ua1[r]);
                float2 q0 = upk(va0[r]), q1 = upk(va1[r]);
                *(float4*)(u + (size_t)row * H + c0) = make_float4(p0.x, p0.y, p1.x, p1.y);
                *(float4*)(v + (size_t)row * H + c0) = make_float4(q0.x, q0.y, q1.x, q1.y);
            }
        }
        __syncwarp();
    }
}

// ---------------- edge classifier: logits = relu(u[s]+v[d]+b1) @ W2 + b2 ----------------
__global__ void edge_kernel(const float* __restrict__ u, const float* __restrict__ v,
                            const int* __restrict__ qs, const int* __restrict__ qd,
                            const float* __restrict__ b1, const float* __restrict__ W2,
                            const float* __restrict__ b2, float* __restrict__ out, int nq) {
    __shared__ float W2s[H * 8];
    __shared__ float b1s[H];
    __shared__ float b2s[8];
    for (int i = threadIdx.x; i < H * 8; i += blockDim.x) W2s[i] = W2[i];
    for (int i = threadIdx.x; i < H; i += blockDim.x) b1s[i] = b1[i];
    if (threadIdx.x < 8) b2s[threadIdx.x] = b2[threadIdx.x];
    __syncthreads();

    int idx = blockIdx.x * blockDim.x + threadIdx.x;
    int stride = gridDim.x * blockDim.x;
    for (int e = idx; e < nq; e += stride) {
        size_t s = (size_t)qs[e];
        size_t d = (size_t)qd[e];
        const float4* ur = (const float4*)(u + s * H);
        const float4* vr = (const float4*)(v + d * H);
        float lg[8];
#pragma unroll
        for (int c = 0; c < 8; c++) lg[c] = b2s[c];
#pragma unroll 8
        for (int k4 = 0; k4 < 32; k4++) {
            float4 a = __ldg(ur + k4);
            float4 b = __ldg(vr + k4);
            float h0 = fmaxf(a.x + b.x + b1s[k4 * 4 + 0], 0.f);
            float h1 = fmaxf(a.y + b.y + b1s[k4 * 4 + 1], 0.f);
            float h2 = fmaxf(a.z + b.z + b1s[k4 * 4 + 2], 0.f);
            float h3 = fmaxf(a.w + b.w + b1s[k4 * 4 + 3], 0.f);
#pragma unroll
            for (int c = 0; c < 8; c++) {
                lg[c] += h0 * W2s[(k4 * 4 + 0) * 8 + c];
                lg[c] += h1 * W2s[(k4 * 4 + 1) * 8 + c];
                lg[c] += h2 * W2s[(k4 * 4 + 2) * 8 + c];
                lg[c] += h3 * W2s[(k4 * 4 + 3) * 8 + c];
            }
        }
        float4* op = (float4*)(out + (size_t)e * 8);
        op[0] = make_float4(lg[0], lg[1], lg[2], lg[3]);
        op[1] = make_float4(lg[4], lg[5], lg[6], lg[7]);
    }
}

// ---------------- host ----------------
#define SMEM_LAYER ((256 * H + WARPS * RPW_L * 256) * 4)  // 128KB + 96KB = 224KB
#define SMEM_UV ((256 * H + WARPS * RPW_UV * 128) * 4)    // 128KB + 32KB = 160KB

extern "C" void kernel_launch(void* const* d_in, const int* in_sizes, int n_in, void* d_out,
                              int out_size) {
    const float* node_emb = (const float*)d_in[0];
    const float* Wl0 = (const float*)d_in[1];
    const float* bl0 = (const float*)d_in[2];
    const float* Wr0 = (const float*)d_in[3];
    const float* Wl1 = (const float*)d_in[4];
    const float* bl1 = (const float*)d_in[5];
    const float* Wr1 = (const float*)d_in[6];
    const float* mW1 = (const float*)d_in[7];
    const float* mb1 = (const float*)d_in[8];
    const float* mW2 = (const float*)d_in[9];
    const float* mb2 = (const float*)d_in[10];
    const int* eidx = (const int*)d_in[11];  // int32 (JAX x64 disabled)
    const int* eq = (const int*)d_in[12];    // int32

    const int n = in_sizes[0] / H;    // 100000
    const int nE = in_sizes[11] / 2;  // 1600000
    const int nq = in_sizes[12] / 2;  // 500000

    float *agg, *deg, *x1, *u, *v;
    cudaGetSymbolAddress((void**)&agg, g_agg);
    cudaGetSymbolAddress((void**)&deg, g_deg);
    cudaGetSymbolAddress((void**)&x1, g_x1);
    cudaGetSymbolAddress((void**)&u, g_u);
    cudaGetSymbolAddress((void**)&v, g_v);

    int sms = 148;
    cudaDeviceGetAttribute(&sms, cudaDevAttrMultiProcessorCount, 0);
    cudaFuncSetAttribute(layer_kernel, cudaFuncAttributeMaxDynamicSharedMemorySize, SMEM_LAYER);
    cudaFuncSetAttribute(uv_kernel, cudaFuncAttributeMaxDynamicSharedMemorySize, SMEM_UV);

    const int n4 = n * H / 4;
    const int scatter_blocks = sms * 16;

    // layer 0
    zero_kernel<<<(n4 + 255) / 256, 256>>>((float4*)agg, n4);
    zero_kernel<<<(n / 4 + 255) / 256, 256>>>((float4*)deg, n / 4);
    scatter_kernel<<<scatter_blocks, 256>>>(node_emb, eidx, eidx + nE, agg, deg, nE);
    layer_kernel<<<sms, TPB, SMEM_LAYER>>>(node_emb, agg, deg, Wl0, Wr0, bl0, x1, n);

    // layer 1 (in-place on x1; row-local so safe)
    zero_kernel<<<(n4 + 255) / 256, 256>>>((float4*)agg, n4);
    scatter_kernel<<<scatter_blocks, 256>>>(x1, eidx, eidx + nE, agg, nullptr, nE);
    layer_kernel<<<sms, TPB, SMEM_LAYER>>>(x1, agg, deg, Wl1, Wr1, bl1, x1, n);

    // edge classifier
    uv_kernel<<<sms, TPB, SMEM_UV>>>(x1, mW1, u, v, n);
    edge_kernel<<<(nq + TPB - 1) / TPB, TPB>>>(u, v, eq, eq + nq, mb1, mW2, mb2, (float*)d_out,
                                               nq);
}

// round 7
// speedup vs baseline: 1.2077x; 1.0240x over previous
#include <cuda_runtime.h>

#define H 128
#define MAXN 100000
#define TPB 512
#define WARPS 16
#define RPL 6      // rows/warp, layer kernel (3 row-pairs)
#define NP_L 3
#define RPUV 6     // rows/warp, uv kernel (3 row-pairs)
#define NP_UV 3

// ---------------- scratch (device globals; no allocations anywhere) ----------------
__device__ __align__(128) float g_agg[MAXN * H];
__device__ __align__(128) float g_deg[MAXN];
__device__ __align__(128) float g_x1[MAXN * H];
__device__ __align__(128) float g_u[MAXN * H];
__device__ __align__(128) float g_v[MAXN * H];

typedef unsigned long long u64;

// ---------------- f32x2 packed helpers ----------------
static __device__ __forceinline__ u64 pk2(float a, float b) {
    u64 r;
    asm("mov.b64 %0, {%1,%2};" : "=l"(r) : "f"(a), "f"(b));
    return r;
}
static __device__ __forceinline__ void fma2(u64& d, u64 a, u64 b) {
    asm("fma.rn.f32x2 %0, %1, %2, %0;" : "+l"(d) : "l"(a), "l"(b));
}
static __device__ __forceinline__ float2 upk(u64 a) {
    float2 r;
    asm("mov.b64 {%0,%1}, %2;" : "=f"(r.x), "=f"(r.y) : "l"(a));
    return r;
}

// ---------------- zero ----------------
__global__ void zero_kernel(float4* p, int n4) {
    int i = blockIdx.x * blockDim.x + threadIdx.x;
    if (i < n4) p[i] = make_float4(0.f, 0.f, 0.f, 0.f);
}

// ---------------- edge scatter: agg[dst] += x[src], deg[dst] += 1 ----------------
__global__ void scatter_kernel(const float* __restrict__ x, const int* __restrict__ src,
                               const int* __restrict__ dst, float* __restrict__ agg,
                               float* __restrict__ deg, int nE) {
    int lane = threadIdx.x & 31;
    int w = (blockIdx.x * blockDim.x + threadIdx.x) >> 5;
    int nw = (gridDim.x * blockDim.x) >> 5;
    for (int e = w; e < nE; e += nw) {
        size_t s = (size_t)src[e];
        size_t d = (size_t)dst[e];
        float4 val = *(const float4*)(x + s * H + (size_t)lane * 4);
        float* p = agg + d * H + (size_t)lane * 4;
        asm volatile("red.global.add.v4.f32 [%0], {%1,%2,%3,%4};" ::"l"(p), "f"(val.x),
                         "f"(val.y), "f"(val.z), "f"(val.w)
                     : "memory");
        if (deg != nullptr && lane == 0) atomicAdd(deg + d, 1.0f);
    }
}

// ---------------- fused SAGE layer: out = relu((agg/max(deg,1))@Wl + x@Wr + b) ----------------
// Row-pair f32x2 packing: acc[rp][c] holds (row 2rp, row 2rp+1) partial sums for col c.
// Staging st[rp][k] = float2(a[2rp][k], a[2rp+1][k]) -> activation operand comes pre-packed
// (broadcast LDS, zero movs); only weights need pk2(w,w) duplication (shared across rows).
__global__ void __launch_bounds__(TPB, 1)
layer_kernel(const float* __restrict__ x, const float* __restrict__ agg,
             const float* __restrict__ deg, const float* __restrict__ Wl,
             const float* __restrict__ Wr, const float* __restrict__ bias,
             float* __restrict__ out, int n) {
    extern __shared__ float sm[];
    float* Ws = sm;                              // 256*128 floats = 128KB (Wl rows then Wr rows)
    float2* stage = (float2*)(sm + 256 * H);     // WARPS * NP_L * 256 float2 = 96KB
    for (int i = threadIdx.x; i < H * H; i += TPB) {
        Ws[i] = Wl[i];
        Ws[H * H + i] = Wr[i];
    }
    __syncthreads();
    const int warp = threadIdx.x >> 5, lane = threadIdx.x & 31;
    const int c0 = lane * 4;
    float2* st = stage + warp * (NP_L * 256);
    const float4 b4 = *(const float4*)(bias + c0);

    for (int base = blockIdx.x * (WARPS * RPL) + warp * RPL; base < n;
         base += gridDim.x * (WARPS * RPL)) {
        // ---- stage: interleave row pairs ----
#pragma unroll
        for (int rp = 0; rp < NP_L; rp++) {
            int r0 = base + 2 * rp, r1 = r0 + 1;
            float4 m0 = make_float4(0.f, 0.f, 0.f, 0.f), m1 = m0, x0 = m0, x1 = m0;
            if (r0 < n) {
                float rd = 1.0f / fmaxf(deg[r0], 1.0f);
                m0 = *(const float4*)(agg + (size_t)r0 * H + c0);
                x0 = *(const float4*)(x + (size_t)r0 * H + c0);
                m0.x *= rd; m0.y *= rd; m0.z *= rd; m0.w *= rd;
            }
            if (r1 < n) {
                float rd = 1.0f / fmaxf(deg[r1], 1.0f);
                m1 = *(const float4*)(agg + (size_t)r1 * H + c0);
                x1 = *(const float4*)(x + (size_t)r1 * H + c0);
                m1.x *= rd; m1.y *= rd; m1.z *= rd; m1.w *= rd;
            }
            float2* b = st + rp * 256;
            *(float4*)(b + c0) = make_float4(m0.x, m1.x, m0.y, m1.y);
            *(float4*)(b + c0 + 2) = make_float4(m0.z, m1.z, m0.w, m1.w);
            *(float4*)(b + 128 + c0) = make_float4(x0.x, x1.x, x0.y, x1.y);
            *(float4*)(b + 128 + c0 + 2) = make_float4(x0.z, x1.z, x0.w, x1.w);
        }
        __syncwarp();

        u64 acc[NP_L][4];
#pragma unroll
        for (int rp = 0; rp < NP_L; rp++)
#pragma unroll
            for (int c = 0; c < 4; c++) acc[rp][c] = 0ull;

#pragma unroll 2
        for (int k4 = 0; k4 < 64; k4++) {
            ulonglong2 ap0[NP_L], ap1[NP_L];
#pragma unroll
            for (int rp = 0; rp < NP_L; rp++) {
                const float2* b = st + rp * 256 + 4 * k4;
                ap0[rp] = *(const ulonglong2*)(b);      // packed pairs for k, k+1
                ap1[rp] = *(const ulonglong2*)(b + 2);  // packed pairs for k+2, k+3
            }
#pragma unroll
            for (int j = 0; j < 4; j++) {
                float4 w = *(const float4*)(Ws + (4 * k4 + j) * H + c0);
                u64 wa = pk2(w.x, w.x), wb = pk2(w.y, w.y);
                u64 wc = pk2(w.z, w.z), wd = pk2(w.w, w.w);
#pragma unroll
                for (int rp = 0; rp < NP_L; rp++) {
                    u64 a = (j == 0) ? ap0[rp].x : (j == 1) ? ap0[rp].y
                                                 : (j == 2) ? ap1[rp].x : ap1[rp].y;
                    fma2(acc[rp][0], wa, a);
                    fma2(acc[rp][1], wb, a);
                    fma2(acc[rp][2], wc, a);
                    fma2(acc[rp][3], wd, a);
                }
            }
        }

#pragma unroll
        for (int rp = 0; rp < NP_L; rp++) {
            int r0 = base + 2 * rp, r1 = r0 + 1;
            float2 v0 = upk(acc[rp][0]), v1 = upk(acc[rp][1]);
            float2 v2 = upk(acc[rp][2]), v3 = upk(acc[rp][3]);
            if (r0 < n)
                *(float4*)(out + (size_t)r0 * H + c0) =
                    make_float4(fmaxf(v0.x + b4.x, 0.f), fmaxf(v1.x + b4.y, 0.f),
                                fmaxf(v2.x + b4.z, 0.f), fmaxf(v3.x + b4.w, 0.f));
            if (r1 < n)
                *(float4*)(out + (size_t)r1 * H + c0) =
                    make_float4(fmaxf(v0.y + b4.x, 0.f), fmaxf(v1.y + b4.y, 0.f),
                                fmaxf(v2.y + b4.z, 0.f), fmaxf(v3.y + b4.w, 0.f));
        }
        __syncwarp();
    }
}

// ---------------- u/v precompute: u = x@W1[0:128,:], v = x@W1[128:256,:] ----------------
// Same row-pair packing; K=128, 8 output cols/lane (4 u + 4 v).
__global__ void __launch_bounds__(TPB, 1)
uv_kernel(const float* __restrict__ x, const float* __restrict__ W1, float* __restrict__ u,
          float* __restrict__ v, int n) {
    extern __shared__ float sm[];
    float* Ws = sm;                           // full W1: 256*128 floats = 128KB
    float2* stage = (float2*)(sm + 256 * H);  // WARPS * NP_UV * 128 float2 = 48KB
    for (int i = threadIdx.x; i < 256 * H; i += TPB) Ws[i] = W1[i];
    __syncthreads();
    const int warp = threadIdx.x >> 5, lane = threadIdx.x & 31;
    const int c0 = lane * 4;
    float2* st = stage + warp * (NP_UV * 128);

    for (int base = blockIdx.x * (WARPS * RPUV) + warp * RPUV; base < n;
         base += gridDim.x * (WARPS * RPUV)) {
#pragma unroll
        for (int rp = 0; rp < NP_UV; rp++) {
            int r0 = base + 2 * rp, r1 = r0 + 1;
            float4 x0 = make_float4(0.f, 0.f, 0.f, 0.f), x1 = x0;
            if (r0 < n) x0 = *(const float4*)(x + (size_t)r0 * H + c0);
            if (r1 < n) x1 = *(const float4*)(x + (size_t)r1 * H + c0);
            float2* b = st + rp * 128;
            *(float4*)(b + c0) = make_float4(x0.x, x1.x, x0.y, x1.y);
            *(float4*)(b + c0 + 2) = make_float4(x0.z, x1.z, x0.w, x1.w);
        }
        __syncwarp();

        u64 au[NP_UV][4], av[NP_UV][4];
#pragma unroll
        for (int rp = 0; rp < NP_UV; rp++)
#pragma unroll
            for (int c = 0; c < 4; c++) { au[rp][c] = 0ull; av[rp][c] = 0ull; }

#pragma unroll 2
        for (int k4 = 0; k4 < 32; k4++) {
            ulonglong2 ap0[NP_UV], ap1[NP_UV];
#pragma unroll
            for (int rp = 0; rp < NP_UV; rp++) {
                const float2* b = st + rp * 128 + 4 * k4;
                ap0[rp] = *(const ulonglong2*)(b);
                ap1[rp] = *(const ulonglong2*)(b + 2);
            }
#pragma unroll
            for (int j = 0; j < 4; j++) {
                int k = 4 * k4 + j;
                float4 wu = *(const float4*)(Ws + k * H + c0);
                float4 wv = *(const float4*)(Ws + (128 + k) * H + c0);
                u64 ua = pk2(wu.x, wu.x), ub = pk2(wu.y, wu.y);
                u64 uc = pk2(wu.z, wu.z), ud = pk2(wu.w, wu.w);
                u64 va = pk2(wv.x, wv.x), vb = pk2(wv.y, wv.y);
                u64 vc = pk2(wv.z, wv.z), vd = pk2(wv.w, wv.w);
#pragma unroll
                for (int rp = 0; rp < NP_UV; rp++) {
                    u64 a = (j == 0) ? ap0[rp].x : (j == 1) ? ap0[rp].y
                                                 : (j == 2) ? ap1[rp].x : ap1[rp].y;
                    fma2(au[rp][0], ua, a);
                    fma2(au[rp][1], ub, a);
                    fma2(au[rp][2], uc, a);
                    fma2(au[rp][3], ud, a);
                    fma2(av[rp][0], va, a);
                    fma2(av[rp][1], vb, a);
                    fma2(av[rp][2], vc, a);
                    fma2(av[rp][3], vd, a);
                }
            }
        }

#pragma unroll
        for (int rp = 0; rp < NP_UV; rp++) {
            int r0 = base + 2 * rp, r1 = r0 + 1;
            float2 a0 = upk(au[rp][0]), a1 = upk(au[rp][1]), a2 = upk(au[rp][2]),
                   a3 = upk(au[rp][3]);
            float2 b0 = upk(av[rp][0]), b1 = upk(av[rp][1]), b2 = upk(av[rp][2]),
                   b3 = upk(av[rp][3]);
            if (r0 < n) {
                *(float4*)(u + (size_t)r0 * H + c0) = make_float4(a0.x, a1.x, a2.x, a3.x);
                *(float4*)(v + (size_t)r0 * H + c0) = make_float4(b0.x, b1.x, b2.x, b3.x);
            }
            if (r1 < n) {
                *(float4*)(u + (size_t)r1 * H + c0) = make_float4(a0.y, a1.y, a2.y, a3.y);
                *(float4*)(v + (size_t)r1 * H + c0) = make_float4(b0.y, b1.y, b2.y, b3.y);
            }
        }
        __syncwarp();
    }
}

// ---------------- edge classifier: logits = relu(u[s]+v[d]+b1) @ W2 + b2 ----------------
__global__ void edge_kernel(const float* __restrict__ u, const float* __restrict__ v,
                            const int* __restrict__ qs, const int* __restrict__ qd,
                            const float* __restrict__ b1, const float* __restrict__ W2,
                            const float* __restrict__ b2, float* __restrict__ out, int nq) {
    __shared__ float W2s[H * 8];
    __shared__ float b1s[H];
    __shared__ float b2s[8];
    for (int i = threadIdx.x; i < H * 8; i += blockDim.x) W2s[i] = W2[i];
    for (int i = threadIdx.x; i < H; i += blockDim.x) b1s[i] = b1[i];
    if (threadIdx.x < 8) b2s[threadIdx.x] = b2[threadIdx.x];
    __syncthreads();

    int idx = blockIdx.x * blockDim.x + threadIdx.x;
    int stride = gridDim.x * blockDim.x;
    for (int e = idx; e < nq; e += stride) {
        size_t s = (size_t)qs[e];
        size_t d = (size_t)qd[e];
        const float4* ur = (const float4*)(u + s * H);
        const float4* vr = (const float4*)(v + d * H);
        float lg[8];
#pragma unroll
        for (int c = 0; c < 8; c++) lg[c] = b2s[c];
#pragma unroll 8
        for (int k4 = 0; k4 < 32; k4++) {
            float4 a = __ldg(ur + k4);
            float4 b = __ldg(vr + k4);
            float h0 = fmaxf(a.x + b.x + b1s[k4 * 4 + 0], 0.f);
            float h1 = fmaxf(a.y + b.y + b1s[k4 * 4 + 1], 0.f);
            float h2 = fmaxf(a.z + b.z + b1s[k4 * 4 + 2], 0.f);
            float h3 = fmaxf(a.w + b.w + b1s[k4 * 4 + 3], 0.f);
#pragma unroll
            for (int c = 0; c < 8; c++) {
                lg[c] += h0 * W2s[(k4 * 4 + 0) * 8 + c];
                lg[c] += h1 * W2s[(k4 * 4 + 1) * 8 + c];
                lg[c] += h2 * W2s[(k4 * 4 + 2) * 8 + c];
                lg[c] += h3 * W2s[(k4 * 4 + 3) * 8 + c];
            }
        }
        float4* op = (float4*)(out + (size_t)e * 8);
        op[0] = make_float4(lg[0], lg[1], lg[2], lg[3]);
        op[1] = make_float4(lg[4], lg[5], lg[6], lg[7]);
    }
}

// ---------------- host ----------------
#define SMEM_LAYER (256 * H * 4 + WARPS * NP_L * 256 * 8)   // 128KB + 96KB = 224KB
#define SMEM_UV (256 * H * 4 + WARPS * NP_UV * 128 * 8)     // 128KB + 48KB = 176KB

extern "C" void kernel_launch(void* const* d_in, const int* in_sizes, int n_in, void* d_out,
                              int out_size) {
    const float* node_emb = (const float*)d_in[0];
    const float* Wl0 = (const float*)d_in[1];
    const float* bl0 = (const float*)d_in[2];
    const float* Wr0 = (const float*)d_in[3];
    const float* Wl1 = (const float*)d_in[4];
    const float* bl1 = (const float*)d_in[5];
    const float* Wr1 = (const float*)d_in[6];
    const float* mW1 = (const float*)d_in[7];
    const float* mb1 = (const float*)d_in[8];
    const float* mW2 = (const float*)d_in[9];
    const float* mb2 = (const float*)d_in[10];
    const int* eidx = (const int*)d_in[11];  // int32 (JAX x64 disabled)
    const int* eq = (const int*)d_in[12];    // int32

    const int n = in_sizes[0] / H;    // 100000
    const int nE = in_sizes[11] / 2;  // 1600000
    const int nq = in_sizes[12] / 2;  // 500000

    float *agg, *deg, *x1, *u, *v;
    cudaGetSymbolAddress((void**)&agg, g_agg);
    cudaGetSymbolAddress((void**)&deg, g_deg);
    cudaGetSymbolAddress((void**)&x1, g_x1);
    cudaGetSymbolAddress((void**)&u, g_u);
    cudaGetSymbolAddress((void**)&v, g_v);

    int sms = 148;
    cudaDeviceGetAttribute(&sms, cudaDevAttrMultiProcessorCount, 0);
    cudaFuncSetAttribute(layer_kernel, cudaFuncAttributeMaxDynamicSharedMemorySize, SMEM_LAYER);
    cudaFuncSetAttribute(uv_kernel, cudaFuncAttributeMaxDynamicSharedMemorySize, SMEM_UV);

    const int n4 = n * H / 4;
    const int scatter_blocks = sms * 16;

    // layer 0
    zero_kernel<<<(n4 + 255) / 256, 256>>>((float4*)agg, n4);
    zero_kernel<<<(n / 4 + 255) / 256, 256>>>((float4*)deg, n / 4);
    scatter_kernel<<<scatter_blocks, 256>>>(node_emb, eidx, eidx + nE, agg, deg, nE);
    layer_kernel<<<sms, TPB, SMEM_LAYER>>>(node_emb, agg, deg, Wl0, Wr0, bl0, x1, n);

    // layer 1 (in-place on x1; row-local so safe)
    zero_kernel<<<(n4 + 255) / 256, 256>>>((float4*)agg, n4);
    scatter_kernel<<<scatter_blocks, 256>>>(x1, eidx, eidx + nE, agg, nullptr, nE);
    layer_kernel<<<sms, TPB, SMEM_LAYER>>>(x1, agg, deg, Wl1, Wr1, bl1, x1, n);

    // edge classifier
    uv_kernel<<<sms, TPB, SMEM_UV>>>(x1, mW1, u, v, n);
    edge_kernel<<<(nq + TPB - 1) / TPB, TPB>>>(u, v, eq, eq + nq, mb1, mW2, mb2, (float*)d_out,
                                               nq);
}